// round 8
// baseline (speedup 1.0000x reference)
#include <cuda_runtime.h>
#include <math.h>

#define CAP 32768
#define NB  32
#define CD  64
#define TOPK 16
#define NCHUNK 2048
#define FULLM 0xFFFFFFFFu
#define PITCHF 132   // m_part/dup-A row pitch in floats (66 pairs, 528B)

typedef unsigned long long ull;

#define FMA2(d, a, b, c) \
    asm("fma.rn.f32x2 %0, %1, %2, %3;" : "=l"(d) : "l"(a), "l"(b), "l"(c))
#define PACK2(d, lo, hi) \
    asm("mov.b64 %0, {%1, %2};" : "=l"(d) : "f"(lo), "f"(hi))

// ---------------- scratch ----------------
__device__ float g_qpart[NB * CD];
__device__ float g_qn[NB * CD];
__device__ float g_scores[NB * CAP];
__device__ float g_cmax[NB * NCHUNK];

__device__ __forceinline__ unsigned ordf(float f) {
    unsigned u = __float_as_uint(f);
    return u ^ ((unsigned)((int)u >> 31) | 0x80000000u);
}
__device__ __forceinline__ float unordf(unsigned k) {
    unsigned u = (k & 0x80000000u) ? (k ^ 0x80000000u) : ~k;
    return __uint_as_float(u);
}

// ---------------- K0: query prep, block per query, 4-way split d-chain ----------------
__global__ __launch_bounds__(256) void k0_prep(
    const float* __restrict__ qc, const float* __restrict__ qctx,
    const float* __restrict__ W1, const float* __restrict__ b1)
{
    __shared__ float sq[64];
    __shared__ float sp[4][64];
    __shared__ float sps[2];
    int b = blockIdx.x, tid = threadIdx.x;
    int h = tid & 63, part = tid >> 6;

    if (tid < 64) sq[tid] = qc[b * CD + tid];
    float v = (tid < 64) ? qctx[b * CD + tid] : 0.0f;
    __syncthreads();

    float s = 0.0f;
    #pragma unroll
    for (int j = 0; j < 16; j++) {
        int d = part * 16 + j;
        s = fmaf(sq[d], W1[d * CD + h], s);
    }
    sp[part][h] = s;

    float ss = v * v;
    #pragma unroll
    for (int o = 16; o; o >>= 1) ss += __shfl_xor_sync(FULLM, ss, o);
    if (tid == 0)  sps[0] = ss;
    if (tid == 32) sps[1] = ss;
    __syncthreads();

    if (tid < 64) {
        g_qpart[b * CD + tid] = sp[0][tid] + sp[1][tid] + sp[2][tid] + sp[3][tid] + b1[tid];
        float inv = 1.0f / fmaxf(sqrtf(sps[0] + sps[1]), 1e-8f);
        g_qn[b * CD + tid] = v * inv;
    }
}

// ---------------- K2: fused GEMM (f32x2, zero in-loop packs) + scalar scoring ----------------
// dynamic smem layout:
//   [0)                sB    : 64*64 floats (W1 bottom half)         16384 B
//   [16384)            sAd   : 4 warps * 16 rows * 528 B (dup-A, then m_part)  33792 B
//   [50176)            s_mx  : 4*2*16 float4                          2048 B
//   [52224)            s_w2  : 16 float4                               256 B
//   [52480)            s_inv : 4*2 floats                               32 B
#define SMEM_K2 52512

__global__ __launch_bounds__(128, 1) void k2_fused(
    const float* __restrict__ mc, const float* __restrict__ mctx,
    const float* __restrict__ fresh,
    const float* __restrict__ W1, const float* __restrict__ W2,
    const float* __restrict__ b2p)
{
    extern __shared__ char dyn[];
    float*  sB   = (float*)dyn;
    float*  sAdF = (float*)(dyn + 16384);          // float view
    ull*    sAdP = (ull*)(dyn + 16384);            // pair view
    float4* s_mx = (float4*)(dyn + 50176);
    float4* s_w2 = (float4*)(dyn + 52224);
    float*  s_inv = (float*)(dyn + 52480);

    int tid = threadIdx.x, w = tid >> 5, lane = tid & 31;
    float* sAw = sAdF + w * (16 * PITCHF);
    ull*   sAwP = sAdP + w * (16 * 66);

    {
        const float4* src = (const float4*)(W1 + 64 * 64);
        float4* dst = (float4*)sB;
        for (int i = tid; i < 1024; i += 128) dst[i] = src[i];
    }
    if (tid < 16) s_w2[tid] = ((const float4*)W2)[tid];
    __syncthreads();

    float b2v = b2p[0];

    // per-lane query vectors (scalar regs)
    float qp[64], qn[64];
    {
        const float4* a4 = (const float4*)(g_qpart + lane * CD);
        const float4* n4 = (const float4*)(g_qn + lane * CD);
        #pragma unroll
        for (int i = 0; i < 16; i++) {
            float4 a = a4[i];
            qp[4 * i + 0] = a.x; qp[4 * i + 1] = a.y; qp[4 * i + 2] = a.z; qp[4 * i + 3] = a.w;
            float4 n = n4[i];
            qn[4 * i + 0] = n.x; qn[4 * i + 1] = n.y; qn[4 * i + 2] = n.z; qn[4 * i + 3] = n.w;
        }
    }

    int rg = lane >> 3;          // 4 rows per lane
    int hg = lane & 7;           // 8 h-cols per lane (4 pairs)
    int half = lane >> 4, q = lane & 15;

    #pragma unroll 1
    for (int it = 0; it < 2; it++) {
        int chunk = blockIdx.x * 8 + w * 2 + it;
        int base = chunk * 16;

        __syncwarp();
        // ---- stage mc rows as DUPLICATED pairs: sAwP[r*66 + d] = (v, v) ----
        {
            const float4* mcp = (const float4*)(mc + (size_t)base * CD);
            #pragma unroll
            for (int j = 0; j < 8; j++) {
                int idx = lane + 32 * j;
                int r = idx >> 4, cc = idx & 15;
                float4 v = mcp[idx];
                ull p0, p1, p2, p3;
                PACK2(p0, v.x, v.x);
                PACK2(p1, v.y, v.y);
                PACK2(p2, v.z, v.z);
                PACK2(p3, v.w, v.w);
                ull* dst = &sAwP[r * 66 + cc * 4];
                dst[0] = p0; dst[1] = p1; dst[2] = p2; dst[3] = p3;
            }
        }
        __syncwarp();

        // ---- GEMM: m_part[r][h] = sum_d mc[r][d] * W1b[d][h] ----
        // acc packed over h: acc[r][hp] covers h = hg*8 + 2*hp + {0,1}
        ull acc[4][4];
        #pragma unroll
        for (int r = 0; r < 4; r++)
            #pragma unroll
            for (int j = 0; j < 4; j++) acc[r][j] = 0ull;

        #pragma unroll 8
        for (int d = 0; d < 64; d++) {
            ull a0 = sAwP[(rg * 4 + 0) * 66 + d];
            ull a1 = sAwP[(rg * 4 + 1) * 66 + d];
            ull a2 = sAwP[(rg * 4 + 2) * 66 + d];
            ull a3 = sAwP[(rg * 4 + 3) * 66 + d];
            ulonglong2 b01 = *(const ulonglong2*)&sB[d * 64 + hg * 8];
            ulonglong2 b23 = *(const ulonglong2*)&sB[d * 64 + hg * 8 + 4];
            FMA2(acc[0][0], a0, b01.x, acc[0][0]);
            FMA2(acc[0][1], a0, b01.y, acc[0][1]);
            FMA2(acc[0][2], a0, b23.x, acc[0][2]);
            FMA2(acc[0][3], a0, b23.y, acc[0][3]);
            FMA2(acc[1][0], a1, b01.x, acc[1][0]);
            FMA2(acc[1][1], a1, b01.y, acc[1][1]);
            FMA2(acc[1][2], a1, b23.x, acc[1][2]);
            FMA2(acc[1][3], a1, b23.y, acc[1][3]);
            FMA2(acc[2][0], a2, b01.x, acc[2][0]);
            FMA2(acc[2][1], a2, b01.y, acc[2][1]);
            FMA2(acc[2][2], a2, b23.x, acc[2][2]);
            FMA2(acc[2][3], a2, b23.y, acc[2][3]);
            FMA2(acc[3][0], a3, b01.x, acc[3][0]);
            FMA2(acc[3][1], a3, b01.y, acc[3][1]);
            FMA2(acc[3][2], a3, b23.x, acc[3][2]);
            FMA2(acc[3][3], a3, b23.y, acc[3][3]);
        }
        __syncwarp();
        // overwrite dup-A region with m_part [r][h] (float view, pitch PITCHF)
        #pragma unroll
        for (int r = 0; r < 4; r++) {
            ulonglong2 lo, hi;
            lo.x = acc[r][0]; lo.y = acc[r][1];
            hi.x = acc[r][2]; hi.y = acc[r][3];
            *(ulonglong2*)&sAw[(rg * 4 + r) * PITCHF + hg * 8] = lo;
            *(ulonglong2*)&sAw[(rg * 4 + r) * PITCHF + hg * 8 + 4] = hi;
        }
        __syncwarp();

        // ---- scoring (scalar, R5 form): 16 rows, 2 at a time; lane = query b ----
        float4 nmx = ((const float4*)(mctx + (size_t)(base + half) * CD))[q];
        float cmax = -1e30f;

        #pragma unroll 1
        for (int pp = 0; pp < 4; pp++) {
            float out4[4];
            #pragma unroll
            for (int p2 = 0; p2 < 2; p2++) {
                int p = 2 * pp + p2;
                int c0 = base + 2 * p;
                s_mx[(w * 2 + half) * 16 + q] = nmx;
                float ssn = nmx.x * nmx.x + nmx.y * nmx.y + nmx.z * nmx.z + nmx.w * nmx.w;
                ssn += __shfl_xor_sync(FULLM, ssn, 1);
                ssn += __shfl_xor_sync(FULLM, ssn, 2);
                ssn += __shfl_xor_sync(FULLM, ssn, 4);
                ssn += __shfl_xor_sync(FULLM, ssn, 8);
                if (q == 0) s_inv[w * 2 + half] = 1.0f / fmaxf(sqrtf(ssn), 1e-8f);
                __syncwarp();
                if (p < 7)
                    nmx = ((const float4*)(mctx + (size_t)(c0 + 2 + half) * CD))[q];
                #pragma unroll
                for (int r = 0; r < 2; r++) {
                    int c = c0 + r;
                    int rl = 2 * p + r;
                    float ac0 = 0.f, ac1 = 0.f, ac2 = 0.f, ac3 = 0.f;
                    float ax0 = 0.f, ax1 = 0.f, ax2 = 0.f, ax3 = 0.f;
                    #pragma unroll
                    for (int i = 0; i < 16; i++) {
                        float4 mp = *(const float4*)&sAw[rl * PITCHF + 4 * i];
                        float4 mx = s_mx[(w * 2 + r) * 16 + i];
                        float4 w2 = s_w2[i];
                        float t0 = fmaxf(qp[4 * i + 0] + mp.x, 0.0f);
                        float t1 = fmaxf(qp[4 * i + 1] + mp.y, 0.0f);
                        float t2 = fmaxf(qp[4 * i + 2] + mp.z, 0.0f);
                        float t3 = fmaxf(qp[4 * i + 3] + mp.w, 0.0f);
                        ac0 = fmaf(t0, w2.x, ac0);
                        ac1 = fmaf(t1, w2.y, ac1);
                        ac2 = fmaf(t2, w2.z, ac2);
                        ac3 = fmaf(t3, w2.w, ac3);
                        ax0 = fmaf(qn[4 * i + 0], mx.x, ax0);
                        ax1 = fmaf(qn[4 * i + 1], mx.y, ax1);
                        ax2 = fmaf(qn[4 * i + 2], mx.z, ax2);
                        ax3 = fmaf(qn[4 * i + 3], mx.w, ax3);
                    }
                    float z   = (ac0 + ac1) + (ac2 + ac3) + b2v;
                    float ctx = ((ax0 + ax1) + (ax2 + ax3)) * s_inv[w * 2 + r];
                    float sig = 1.0f / (1.0f + __expf(-z));
                    float score = 0.5f * sig + 0.3f * ctx + 0.2f * fresh[c];
                    out4[2 * p2 + r] = score;
                    cmax = fmaxf(cmax, score);
                }
                __syncwarp();
            }
            *(float4*)&g_scores[(size_t)lane * CAP + base + 4 * pp] =
                make_float4(out4[0], out4[1], out4[2], out4[3]);
        }
        g_cmax[lane * NCHUNK + chunk] = cmax;
    }
}

// ---------------- K3: threshold-filter top-16 + gather ----------------
__global__ __launch_bounds__(256) void k3_topk(
    const float* __restrict__ mc, const float* __restrict__ fresh,
    float* __restrict__ out)
{
    __shared__ unsigned s_key[NCHUNK];
    __shared__ unsigned s_tm[256];
    __shared__ unsigned s_tau;
    __shared__ int s_cnt, s_cnt2;
    __shared__ int s_cand[64];
    __shared__ unsigned s_ekey[64];
    __shared__ int s_eidx[64];
    __shared__ int s_sel[TOPK];
    __shared__ float s_val[TOPK];

    int b = blockIdx.x;
    int tid = threadIdx.x;
    int lane = tid & 31;

    unsigned tmax = 0;
    #pragma unroll
    for (int j = 0; j < 8; j++) {
        unsigned k = ordf(g_cmax[b * NCHUNK + tid * 8 + j]);
        s_key[tid * 8 + j] = k;
        tmax = max(tmax, k);
    }
    s_tm[tid] = tmax;
    if (tid == 0) { s_cnt = 0; s_cnt2 = 0; }
    if (tid < 64) s_ekey[tid] = 0u;
    __syncthreads();

    if (tid < 32) {
        unsigned gm = 0;
        #pragma unroll
        for (int j = 0; j < 8; j++) gm = max(gm, s_tm[lane * 8 + j]);
        int rank = 0;
        #pragma unroll
        for (int j = 0; j < 32; j++) {
            unsigned vj = __shfl_sync(FULLM, gm, j);
            rank += (vj > gm) || (vj == gm && j < lane);
        }
        unsigned eq = __ballot_sync(FULLM, rank == 15);
        unsigned tau = __shfl_sync(FULLM, gm, __ffs(eq) - 1);
        if (lane == 0) s_tau = tau;
    }
    __syncthreads();
    unsigned tau = s_tau;

    #pragma unroll
    for (int j = 0; j < 8; j++) {
        int ch = tid * 8 + j;
        if (s_key[ch] >= tau) {
            int p = atomicAdd(&s_cnt, 1);
            if (p < 64) s_cand[p] = ch;
        }
    }
    __syncthreads();
    int cnt = min(s_cnt, 64);

    for (int i = tid; i < cnt * 16; i += 256) {
        int ch = s_cand[i >> 4];
        int gi = ch * 16 + (i & 15);
        unsigned key = ordf(g_scores[(size_t)b * CAP + gi]);
        if (key >= tau) {
            int p = atomicAdd(&s_cnt2, 1);
            if (p < 64) { s_ekey[p] = key; s_eidx[p] = gi; }
        }
    }
    __syncthreads();

    if (tid < 32) {
        for (int k = 0; k < TOPK; k++) {
            unsigned lkey = 0; int lidx = 0x7FFFFFFF; int lpos = -1;
            #pragma unroll
            for (int j = 0; j < 2; j++) {
                int p = lane + 32 * j;
                unsigned kk = s_ekey[p];
                int ii = s_eidx[p];
                if (kk > lkey || (kk == lkey && kk != 0u && ii < lidx)) {
                    lkey = kk; lidx = ii; lpos = p;
                }
            }
            unsigned m = __reduce_max_sync(FULLM, lkey);
            int cand = (lkey == m) ? lidx : 0x7FFFFFFF;
            int gi = __reduce_min_sync(FULLM, cand);
            if (lane == 0) { s_sel[k] = gi; s_val[k] = unordf(m); }
            if (lkey == m && lidx == gi) s_ekey[lpos] = 0u;
            __syncwarp();
        }
    }
    __syncthreads();

    for (int i = tid; i < TOPK * CD; i += 256) {
        int k = i >> 6, h = i & 63;
        out[(size_t)b * (TOPK * CD) + i] = mc[(size_t)s_sel[k] * CD + h];
    }
    if (tid < TOPK) {
        out[NB * TOPK * CD + b * TOPK + tid] = s_val[tid];
        out[NB * TOPK * CD + NB * TOPK + b * TOPK + tid] = fresh[s_sel[tid]];
    }
}

// ---------------- launch ----------------
extern "C" void kernel_launch(void* const* d_in, const int* in_sizes, int n_in,
                              void* d_out, int out_size)
{
    const float* qc    = (const float*)d_in[0];
    const float* qctx  = (const float*)d_in[1];
    const float* mc    = (const float*)d_in[2];
    const float* mctx  = (const float*)d_in[3];
    const float* fresh = (const float*)d_in[4];
    const float* W1    = (const float*)d_in[5];
    const float* b1    = (const float*)d_in[6];
    const float* W2    = (const float*)d_in[7];
    const float* b2    = (const float*)d_in[8];
    float* out = (float*)d_out;

    cudaFuncSetAttribute(k2_fused, cudaFuncAttributeMaxDynamicSharedMemorySize, SMEM_K2);

    k0_prep<<<NB, 256>>>(qc, qctx, W1, b1);
    k2_fused<<<NCHUNK / 8, 128, SMEM_K2>>>(mc, mctx, fresh, W1, W2, b2);
    k3_topk<<<NB, 256>>>(mc, fresh, out);
}